// round 15
// baseline (speedup 1.0000x reference)
#include <cuda_runtime.h>
#include <cuda_fp16.h>

#define IH 256
#define IW 256
#define NPIX (IH * IW)
#define NMAPS 88
#define SRC_ELEMS (NPIX * 3)

#define QSTRIDE 132
#define QROWS 129
#define COPYSZ (QROWS * QSTRIDE)      // 17028

#define BP 258                        // padded b-plane dim (rows/cols -1..256)
#define BPL_PAD 66568                 // 258*258=66564 halves, padded to 16B
#define SMEMB (BPL_PAD * 2)           // 133136 bytes

#define NG8 (NMAPS * NPIX / 8)        // 720,896 sample-groups of 8
#define PBLK 1024
#define PGRD 148
#define PSTRIDE (PBLK * PGRD)         // 151552

#define PACK_THREADS 192
#define NQBLK (4 * QROWS)             // 516 quad-pack blocks
#define NBBLK 87                      // b-plane blocks (87*192*4 >= 66568)
#define ROWF (IW * 3)

// rg-quad: 2x2 corners, each corner = half2(r,g). [nw,ne,sw,se] = 16B.
// Copy (py,px): quad (ky,kx) covers rows (2ky-py, 2ky-py+1), cols (2kx-px, 2kx-px+1).
// OOB corners stored zero (bakes the reference's corner masks).
__device__ uint4 g_rgq[4 * COPYSZ];                      // ~1.09 MB
__device__ __align__(16) unsigned short g_bpl[BPL_PAD];  // padded fp16 b-plane

__global__ void __launch_bounds__(PACK_THREADS) pack_src_kernel(
    const float* __restrict__ src) {
    if (blockIdx.x >= NQBLK) {
        // ---- b-plane fill: 4 halves per thread (8B stores) ----
        int j0 = ((blockIdx.x - NQBLK) * PACK_THREADS + threadIdx.x) * 4;
        if (j0 < BPL_PAD) {
            unsigned short v[4];
#pragma unroll
            for (int k = 0; k < 4; k++) {
                int j = j0 + k;
                int r = j / BP - 1;
                int c = j % BP - 1;
                __half h = (j < BP * BP && (unsigned)r < IH && (unsigned)c < IW)
                             ? __float2half(src[(r * IW + c) * 3 + 2])
                             : __float2half(0.f);
                v[k] = *reinterpret_cast<unsigned short*>(&h);
            }
            *reinterpret_cast<uint2*>(&g_bpl[j0]) = *reinterpret_cast<uint2*>(v);
        }
        return;
    }

    // ---- rg quad pack: one CTA per (copy, quad-row), coalesced via smem ----
    __shared__ float srow[2 * ROWF];
    int copy = blockIdx.x / QROWS;
    int ky   = blockIdx.x % QROWS;
    int py = copy >> 1, px = copy & 1;
    int r0 = 2 * ky - py;

    const float4* s4 = reinterpret_cast<const float4*>(src);
    float4* sm4 = reinterpret_cast<float4*>(srow);
#pragma unroll
    for (int h = 0; h < 2; h++) {
        int i = threadIdx.x + h * PACK_THREADS;
        int rr = i / (ROWF / 4);
        int cc = i % (ROWF / 4);
        int gr = r0 + rr;
        float4 v = make_float4(0.f, 0.f, 0.f, 0.f);
        if ((unsigned)gr < IH) v = s4[gr * (ROWF / 4) + cc];
        sm4[i] = v;
    }
    __syncthreads();

    int kx = threadIdx.x;
    if (kx >= QSTRIDE) return;
    int c0 = 2 * kx - px;

    unsigned w[4];
#pragma unroll
    for (int k = 0; k < 4; k++) {       // 0=NW 1=NE 2=SW 3=SE
        int rr = k >> 1;
        int cc = c0 + (k & 1);
        if (((unsigned)(r0 + rr) < IH) && ((unsigned)cc < IW)) {
            const float* p = srow + rr * ROWF + cc * 3;
            __half2 h = __halves2half2(__float2half(p[0]), __float2half(p[1]));
            w[k] = *reinterpret_cast<unsigned*>(&h);
        } else {
            w[k] = 0u;
        }
    }
    g_rgq[copy * COPYSZ + ky * QSTRIDE + kx] = make_uint4(w[0], w[1], w[2], w[3]);
}

__device__ __forceinline__ float2 u2f(unsigned v) {
    __half2 h = *reinterpret_cast<__half2*>(&v);
    return __half22float2(h);
}

// Persistent: 148 CTAs x 1024 thr, b-plane in smem, 8 samples/thread/iter.
__global__ void __launch_bounds__(PBLK, 1) deform_kernel(
    const float* __restrict__ motions, float* __restrict__ out) {
    extern __shared__ __half sb[];

    // fill smem b-plane (16B coalesced)
    {
        const uint4* gq = reinterpret_cast<const uint4*>(g_bpl);
        uint4* sq = reinterpret_cast<uint4*>(sb);
        for (int i = threadIdx.x; i < BPL_PAD / 8; i += PBLK)
            sq[i] = gq[i];
    }
    __syncthreads();

    for (int t = blockIdx.x * PBLK + threadIdx.x; t < NG8; t += PSTRIDE) {
        // motions for 8 pixels: two 32B streaming loads
        const float* mbase = motions + (size_t)t * 16;
        float mv[16];
        asm("ld.global.cs.v8.f32 {%0,%1,%2,%3,%4,%5,%6,%7}, [%8];"
            : "=f"(mv[0]), "=f"(mv[1]), "=f"(mv[2]), "=f"(mv[3]),
              "=f"(mv[4]), "=f"(mv[5]), "=f"(mv[6]), "=f"(mv[7])
            : "l"(mbase));
        asm("ld.global.cs.v8.f32 {%0,%1,%2,%3,%4,%5,%6,%7}, [%8];"
            : "=f"(mv[8]),  "=f"(mv[9]),  "=f"(mv[10]), "=f"(mv[11]),
              "=f"(mv[12]), "=f"(mv[13]), "=f"(mv[14]), "=f"(mv[15])
            : "l"(mbase + 8));

        // address phase: pk = ((yn+1)<<9) | (xw+1); mv -> fx,fy
        int pk[8];
#pragma unroll
        for (int s = 0; s < 8; s++) {
            float x = fmaf(mv[s * 2 + 0], 128.f, 127.5f);   // [-0.5, 255.5)
            float y = fmaf(mv[s * 2 + 1], 128.f, 127.5f);
            int xw = __float2int_rd(x);   // [-1, 255]
            int yn = __float2int_rd(y);   // [-1, 255]
            mv[s * 2 + 0] = x - (float)xw;
            mv[s * 2 + 1] = y - (float)yn;
            pk[s] = ((yn + 1) << 9) | (xw + 1);
        }

        // 8 rg gathers (LDG.128), back-to-back
        uint4 q[8];
#pragma unroll
        for (int s = 0; s < 8; s++) {
            int row = pk[s] >> 9;        // yn+1
            int col = pk[s] & 511;       // xw+1
            int yn = row - 1, xw = col - 1;
            int py = yn & 1, px = xw & 1;
            int off = ((py << 1) | px) * COPYSZ
                    + (((yn + py) >> 1) * QSTRIDE)
                    + ((xw + px) >> 1);
            q[s] = __ldg(&g_rgq[off]);
        }

        // consume in issue order; b from smem (4 LDS.16/sample);
        // results overwrite q[s].x/y/z as float bits.
#pragma unroll
        for (int s = 0; s < 8; s++) {
            int bb = (pk[s] >> 9) * BP + (pk[s] & 511);
            float bnw = __half2float(sb[bb]);
            float bne = __half2float(sb[bb + 1]);
            float bsw = __half2float(sb[bb + BP]);
            float bse = __half2float(sb[bb + BP + 1]);

            float fx = mv[s * 2 + 0];
            float fy = mv[s * 2 + 1];
            float wnw = (1.f - fy) * (1.f - fx);
            float wne = (1.f - fy) * fx;
            float wsw = fy * (1.f - fx);
            float wse = fy * fx;

            float2 nw = u2f(q[s].x), ne = u2f(q[s].y);
            float2 sw = u2f(q[s].z), se = u2f(q[s].w);

            float R = wnw * nw.x + wne * ne.x + wsw * sw.x + wse * se.x;
            float G = wnw * nw.y + wne * ne.y + wsw * sw.y + wse * se.y;
            float B = wnw * bnw  + wne * bne  + wsw * bsw  + wse * bse;
            q[s].x = __float_as_uint(R);
            q[s].y = __float_as_uint(G);
            q[s].z = __float_as_uint(B);
        }

        // 96B contiguous, 32B-aligned: three 256-bit streaming stores
        float* obase = out + (size_t)t * 24;
        asm volatile("st.global.cs.v8.f32 [%0], {%1,%2,%3,%4,%5,%6,%7,%8};"
            :: "l"(obase),
               "r"(q[0].x), "r"(q[0].y), "r"(q[0].z), "r"(q[1].x),
               "r"(q[1].y), "r"(q[1].z), "r"(q[2].x), "r"(q[2].y)
            : "memory");
        asm volatile("st.global.cs.v8.f32 [%0], {%1,%2,%3,%4,%5,%6,%7,%8};"
            :: "l"(obase + 8),
               "r"(q[2].z), "r"(q[3].x), "r"(q[3].y), "r"(q[3].z),
               "r"(q[4].x), "r"(q[4].y), "r"(q[4].z), "r"(q[5].x)
            : "memory");
        asm volatile("st.global.cs.v8.f32 [%0], {%1,%2,%3,%4,%5,%6,%7,%8};"
            :: "l"(obase + 16),
               "r"(q[5].y), "r"(q[5].z), "r"(q[6].x), "r"(q[6].y),
               "r"(q[6].z), "r"(q[7].x), "r"(q[7].y), "r"(q[7].z)
            : "memory");
    }
}

extern "C" void kernel_launch(void* const* d_in, const int* in_sizes, int n_in,
                              void* d_out, int out_size) {
    const float* source  = (const float*)d_in[0];
    const float* motions = (const float*)d_in[1];
    if (n_in >= 2 && in_sizes[0] != SRC_ELEMS) {
        source  = (const float*)d_in[1];
        motions = (const float*)d_in[0];
    }

    cudaFuncSetAttribute(deform_kernel,
                         cudaFuncAttributeMaxDynamicSharedMemorySize, SMEMB);

    pack_src_kernel<<<NQBLK + NBBLK, PACK_THREADS>>>(source);
    deform_kernel<<<PGRD, PBLK, SMEMB>>>(motions, (float*)d_out);
}

// round 16
// speedup vs baseline: 1.0457x; 1.0457x over previous
#include <cuda_runtime.h>
#include <cuda_fp16.h>

#define IH 256
#define IW 256
#define NPIX (IH * IW)
#define NMAPS 88
#define SRC_ELEMS (NPIX * 3)

#define QSTRIDE 132
#define QROWS 129
#define COPYSZ (QROWS * QSTRIDE)    // 17028

#define NG8 (NMAPS * NPIX / 8)      // 720,896 threads (8 px each)
#define DTHREADS 256
#define NDEFB (NG8 / DTHREADS)      // 2816

#define PACK_THREADS 192
#define ROWF (IW * 3)

// 2x2 fp16 quad, 32B: [0..3]=NW(r,g,b,0) [4..7]=NE [8..11]=SW [12..15]=SE.
// Copy (py,px): quad (ky,kx) covers rows (2ky-py, 2ky-py+1), cols (2kx-px, 2kx-px+1).
// OOB pixels stored zero -> bakes the reference's corner masks.
struct __align__(32) Quad { uint4 a, b; };
__device__ Quad g_quads[4 * COPYSZ];   // ~2.18 MB, L2-resident (evict_last)

__global__ void __launch_bounds__(PACK_THREADS) pack_src_kernel(
    const float* __restrict__ src) {
    __shared__ float srow[2 * ROWF];

    int copy = blockIdx.x / QROWS;
    int ky   = blockIdx.x % QROWS;
    int py = copy >> 1, px = copy & 1;
    int r0 = 2 * ky - py;

    const float4* s4 = reinterpret_cast<const float4*>(src);
    float4* sm4 = reinterpret_cast<float4*>(srow);
#pragma unroll
    for (int h = 0; h < 2; h++) {
        int i = threadIdx.x + h * PACK_THREADS;
        int rr = i / (ROWF / 4);
        int cc = i % (ROWF / 4);
        int gr = r0 + rr;
        float4 v = make_float4(0.f, 0.f, 0.f, 0.f);
        if ((unsigned)gr < IH) v = s4[gr * (ROWF / 4) + cc];
        sm4[i] = v;
    }
    __syncthreads();

    int kx = threadIdx.x;
    if (kx >= QSTRIDE) return;
    int c0 = 2 * kx - px;

    __align__(32) __half hh[16];
#pragma unroll
    for (int k = 0; k < 4; k++) {       // 0=NW 1=NE 2=SW 3=SE
        int rr = k >> 1;
        int cc = c0 + (k & 1);
        bool ok = ((unsigned)(r0 + rr) < IH) && ((unsigned)cc < IW);
        if (ok) {
            const float* p = srow + rr * ROWF + cc * 3;
            hh[k * 4 + 0] = __float2half(p[0]);
            hh[k * 4 + 1] = __float2half(p[1]);
            hh[k * 4 + 2] = __float2half(p[2]);
            hh[k * 4 + 3] = __float2half(0.f);
        } else {
            hh[k * 4 + 0] = hh[k * 4 + 1] = hh[k * 4 + 2] = hh[k * 4 + 3] =
                __float2half(0.f);
        }
    }
    g_quads[copy * COPYSZ + ky * QSTRIDE + kx] = *reinterpret_cast<Quad*>(hh);
}

__device__ __forceinline__ float2 h2f(float v) {
    __half2 h = *reinterpret_cast<__half2*>(&v);
    return __half22float2(h);
}

// 8 samples/thread; <=64 regs (4 CTAs/SM) keeps all 8 LDG.256 in flight.
__global__ void __launch_bounds__(DTHREADS, 4) deform_kernel(
    const float* __restrict__ motions, float* __restrict__ out) {
    int t = blockIdx.x * DTHREADS + threadIdx.x;

    const float* mbase = motions + (size_t)t * 16;
    float mv[16];
    asm("ld.global.cs.v8.f32 {%0,%1,%2,%3,%4,%5,%6,%7}, [%8];"
        : "=f"(mv[0]), "=f"(mv[1]), "=f"(mv[2]), "=f"(mv[3]),
          "=f"(mv[4]), "=f"(mv[5]), "=f"(mv[6]), "=f"(mv[7])
        : "l"(mbase));
    asm("ld.global.cs.v8.f32 {%0,%1,%2,%3,%4,%5,%6,%7}, [%8];"
        : "=f"(mv[8]),  "=f"(mv[9]),  "=f"(mv[10]), "=f"(mv[11]),
          "=f"(mv[12]), "=f"(mv[13]), "=f"(mv[14]), "=f"(mv[15])
        : "l"(mbase + 8));

    // address math; afterwards mv[2s]=fx, mv[2s+1]=fy (keeps live regs low)
    const Quad* qp[8];
#pragma unroll
    for (int s = 0; s < 8; s++) {
        float x = fmaf(mv[s * 2 + 0], 128.f, 127.5f);   // [-0.5, 255.5)
        float y = fmaf(mv[s * 2 + 1], 128.f, 127.5f);
        int xw = __float2int_rd(x);   // [-1, 255]
        int yn = __float2int_rd(y);   // [-1, 255]
        mv[s * 2 + 0] = x - (float)xw;
        mv[s * 2 + 1] = y - (float)yn;
        int py = yn & 1, px = xw & 1;
        int ky = (yn + py) >> 1;
        int kx = (xw + px) >> 1;
        qp[s] = &g_quads[((py << 1) | px) * COPYSZ + ky * QSTRIDE + kx];
    }

    // 8 divergent 256-bit gathers, back-to-back, L2 evict_last (keep quads hot)
    float q[8][8];
#pragma unroll
    for (int s = 0; s < 8; s++) {
        asm("ld.global.nc.L2::evict_last.v8.f32 {%0,%1,%2,%3,%4,%5,%6,%7}, [%8];"
            : "=f"(q[s][0]), "=f"(q[s][1]), "=f"(q[s][2]), "=f"(q[s][3]),
              "=f"(q[s][4]), "=f"(q[s][5]), "=f"(q[s][6]), "=f"(q[s][7])
            : "l"(qp[s]));
    }

    // consume in issue order; results overwrite q[s][0..2]
#pragma unroll
    for (int s = 0; s < 8; s++) {
        float fx = mv[s * 2 + 0];
        float fy = mv[s * 2 + 1];
        float wnw = (1.f - fy) * (1.f - fx);
        float wne = (1.f - fy) * fx;
        float wsw = fy * (1.f - fx);
        float wse = fy * fx;

        float2 nw = h2f(q[s][0]);
        float2 ne = h2f(q[s][2]);
        float2 sw = h2f(q[s][4]);
        float2 se = h2f(q[s][6]);
        float nwb = h2f(q[s][1]).x;
        float neb = h2f(q[s][3]).x;
        float swb = h2f(q[s][5]).x;
        float seb = h2f(q[s][7]).x;

        q[s][0] = wnw * nw.x + wne * ne.x + wsw * sw.x + wse * se.x;
        q[s][1] = wnw * nw.y + wne * ne.y + wsw * sw.y + wse * se.y;
        q[s][2] = wnw * nwb  + wne * neb  + wsw * swb  + wse * seb;
    }

    // 96B contiguous, 32B-aligned: three 256-bit streaming stores.
    float* obase = out + (size_t)t * 24;
    asm volatile("st.global.cs.v8.f32 [%0], {%1,%2,%3,%4,%5,%6,%7,%8};"
        :: "l"(obase),
           "f"(q[0][0]), "f"(q[0][1]), "f"(q[0][2]), "f"(q[1][0]),
           "f"(q[1][1]), "f"(q[1][2]), "f"(q[2][0]), "f"(q[2][1])
        : "memory");
    asm volatile("st.global.cs.v8.f32 [%0], {%1,%2,%3,%4,%5,%6,%7,%8};"
        :: "l"(obase + 8),
           "f"(q[2][2]), "f"(q[3][0]), "f"(q[3][1]), "f"(q[3][2]),
           "f"(q[4][0]), "f"(q[4][1]), "f"(q[4][2]), "f"(q[5][0])
        : "memory");
    asm volatile("st.global.cs.v8.f32 [%0], {%1,%2,%3,%4,%5,%6,%7,%8};"
        :: "l"(obase + 16),
           "f"(q[5][1]), "f"(q[5][2]), "f"(q[6][0]), "f"(q[6][1]),
           "f"(q[6][2]), "f"(q[7][0]), "f"(q[7][1]), "f"(q[7][2])
        : "memory");
}

extern "C" void kernel_launch(void* const* d_in, const int* in_sizes, int n_in,
                              void* d_out, int out_size) {
    const float* source  = (const float*)d_in[0];
    const float* motions = (const float*)d_in[1];
    if (n_in >= 2 && in_sizes[0] != SRC_ELEMS) {
        source  = (const float*)d_in[1];
        motions = (const float*)d_in[0];
    }

    // deform uses no smem: give it the full L1D carveout for quad caching
    static bool configured = false;
    if (!configured) {
        cudaFuncSetAttribute(deform_kernel,
                             cudaFuncAttributePreferredSharedMemoryCarveout,
                             cudaSharedmemCarveoutMaxL1);
        configured = true;
    }

    pack_src_kernel<<<4 * QROWS, PACK_THREADS>>>(source);
    deform_kernel<<<NDEFB, DTHREADS>>>(motions, (float*)d_out);
}

// round 17
// speedup vs baseline: 1.0494x; 1.0035x over previous
#include <cuda_runtime.h>
#include <cuda_fp16.h>

#define IH 256
#define IW 256
#define NPIX (IH * IW)
#define NMAPS 88
#define SRC_ELEMS (NPIX * 3)

#define QSTRIDE 132
#define QROWS 129
#define COPYSZ (QROWS * QSTRIDE)    // 17028

#define NG8 (NMAPS * NPIX / 8)      // 720,896 threads (8 px each)
#define DTHREADS 256
#define NDEFB (NG8 / DTHREADS)      // 2816

#define PACK_THREADS 192
#define ROWF (IW * 3)

// 2x2 fp16 quad, 32B: [0..3]=NW(r,g,b,0) [4..7]=NE [8..11]=SW [12..15]=SE.
// Copy (py,px): quad (ky,kx) covers rows (2ky-py, 2ky-py+1), cols (2kx-px, 2kx-px+1).
// OOB pixels stored zero -> bakes the reference's corner masks.
struct __align__(32) Quad { uint4 a, b; };
__device__ Quad g_quads[4 * COPYSZ];   // ~2.18 MB, L2-resident

__global__ void __launch_bounds__(PACK_THREADS) pack_src_kernel(
    const float* __restrict__ src) {
    __shared__ float srow[2 * ROWF];

    int copy = blockIdx.x / QROWS;
    int ky   = blockIdx.x % QROWS;
    int py = copy >> 1, px = copy & 1;
    int r0 = 2 * ky - py;

    const float4* s4 = reinterpret_cast<const float4*>(src);
    float4* sm4 = reinterpret_cast<float4*>(srow);
#pragma unroll
    for (int h = 0; h < 2; h++) {
        int i = threadIdx.x + h * PACK_THREADS;
        int rr = i / (ROWF / 4);
        int cc = i % (ROWF / 4);
        int gr = r0 + rr;
        float4 v = make_float4(0.f, 0.f, 0.f, 0.f);
        if ((unsigned)gr < IH) v = s4[gr * (ROWF / 4) + cc];
        sm4[i] = v;
    }
    __syncthreads();

    int kx = threadIdx.x;
    if (kx >= QSTRIDE) return;
    int c0 = 2 * kx - px;

    __align__(32) __half hh[16];
#pragma unroll
    for (int k = 0; k < 4; k++) {       // 0=NW 1=NE 2=SW 3=SE
        int rr = k >> 1;
        int cc = c0 + (k & 1);
        bool ok = ((unsigned)(r0 + rr) < IH) && ((unsigned)cc < IW);
        if (ok) {
            const float* p = srow + rr * ROWF + cc * 3;
            hh[k * 4 + 0] = __float2half(p[0]);
            hh[k * 4 + 1] = __float2half(p[1]);
            hh[k * 4 + 2] = __float2half(p[2]);
            hh[k * 4 + 3] = __float2half(0.f);
        } else {
            hh[k * 4 + 0] = hh[k * 4 + 1] = hh[k * 4 + 2] = hh[k * 4 + 3] =
                __float2half(0.f);
        }
    }
    g_quads[copy * COPYSZ + ky * QSTRIDE + kx] = *reinterpret_cast<Quad*>(hh);
}

__device__ __forceinline__ float2 h2f(float v) {
    __half2 h = *reinterpret_cast<__half2*>(&v);
    return __half22float2(h);
}

// 8 samples/thread; <=64 regs (4 CTAs/SM) keeps all 8 LDG.256 in flight.
// PDL: prologue (motions + address math) overlaps the pack kernel.
__global__ void __launch_bounds__(DTHREADS, 4) deform_kernel(
    const float* __restrict__ motions, float* __restrict__ out) {
    int t = blockIdx.x * DTHREADS + threadIdx.x;

    const float* mbase = motions + (size_t)t * 16;
    float mv[16];
    asm("ld.global.cs.v8.f32 {%0,%1,%2,%3,%4,%5,%6,%7}, [%8];"
        : "=f"(mv[0]), "=f"(mv[1]), "=f"(mv[2]), "=f"(mv[3]),
          "=f"(mv[4]), "=f"(mv[5]), "=f"(mv[6]), "=f"(mv[7])
        : "l"(mbase));
    asm("ld.global.cs.v8.f32 {%0,%1,%2,%3,%4,%5,%6,%7}, [%8];"
        : "=f"(mv[8]),  "=f"(mv[9]),  "=f"(mv[10]), "=f"(mv[11]),
          "=f"(mv[12]), "=f"(mv[13]), "=f"(mv[14]), "=f"(mv[15])
        : "l"(mbase + 8));

    // address math; afterwards mv[2s]=fx, mv[2s+1]=fy (keeps live regs low)
    const Quad* qp[8];
#pragma unroll
    for (int s = 0; s < 8; s++) {
        float x = fmaf(mv[s * 2 + 0], 128.f, 127.5f);   // [-0.5, 255.5)
        float y = fmaf(mv[s * 2 + 1], 128.f, 127.5f);
        int xw = __float2int_rd(x);   // [-1, 255]
        int yn = __float2int_rd(y);   // [-1, 255]
        mv[s * 2 + 0] = x - (float)xw;
        mv[s * 2 + 1] = y - (float)yn;
        int py = yn & 1, px = xw & 1;
        int ky = (yn + py) >> 1;
        int kx = (xw + px) >> 1;
        qp[s] = &g_quads[((py << 1) | px) * COPYSZ + ky * QSTRIDE + kx];
    }

    // gate on pack completion only now (PDL)
    cudaGridDependencySynchronize();

    // 8 divergent 256-bit gathers, back-to-back.
    float q[8][8];
#pragma unroll
    for (int s = 0; s < 8; s++) {
        asm("ld.global.nc.v8.f32 {%0,%1,%2,%3,%4,%5,%6,%7}, [%8];"
            : "=f"(q[s][0]), "=f"(q[s][1]), "=f"(q[s][2]), "=f"(q[s][3]),
              "=f"(q[s][4]), "=f"(q[s][5]), "=f"(q[s][6]), "=f"(q[s][7])
            : "l"(qp[s]));
    }

    // consume in issue order; results overwrite q[s][0..2]
#pragma unroll
    for (int s = 0; s < 8; s++) {
        float fx = mv[s * 2 + 0];
        float fy = mv[s * 2 + 1];
        float wnw = (1.f - fy) * (1.f - fx);
        float wne = (1.f - fy) * fx;
        float wsw = fy * (1.f - fx);
        float wse = fy * fx;

        float2 nw = h2f(q[s][0]);
        float2 ne = h2f(q[s][2]);
        float2 sw = h2f(q[s][4]);
        float2 se = h2f(q[s][6]);
        float nwb = h2f(q[s][1]).x;
        float neb = h2f(q[s][3]).x;
        float swb = h2f(q[s][5]).x;
        float seb = h2f(q[s][7]).x;

        q[s][0] = wnw * nw.x + wne * ne.x + wsw * sw.x + wse * se.x;
        q[s][1] = wnw * nw.y + wne * ne.y + wsw * sw.y + wse * se.y;
        q[s][2] = wnw * nwb  + wne * neb  + wsw * swb  + wse * seb;
    }

    // 96B contiguous, 32B-aligned: three 256-bit streaming stores.
    float* obase = out + (size_t)t * 24;
    asm volatile("st.global.cs.v8.f32 [%0], {%1,%2,%3,%4,%5,%6,%7,%8};"
        :: "l"(obase),
           "f"(q[0][0]), "f"(q[0][1]), "f"(q[0][2]), "f"(q[1][0]),
           "f"(q[1][1]), "f"(q[1][2]), "f"(q[2][0]), "f"(q[2][1])
        : "memory");
    asm volatile("st.global.cs.v8.f32 [%0], {%1,%2,%3,%4,%5,%6,%7,%8};"
        :: "l"(obase + 8),
           "f"(q[2][2]), "f"(q[3][0]), "f"(q[3][1]), "f"(q[3][2]),
           "f"(q[4][0]), "f"(q[4][1]), "f"(q[4][2]), "f"(q[5][0])
        : "memory");
    asm volatile("st.global.cs.v8.f32 [%0], {%1,%2,%3,%4,%5,%6,%7,%8};"
        :: "l"(obase + 16),
           "f"(q[5][1]), "f"(q[5][2]), "f"(q[6][0]), "f"(q[6][1]),
           "f"(q[6][2]), "f"(q[7][0]), "f"(q[7][1]), "f"(q[7][2])
        : "memory");
}

extern "C" void kernel_launch(void* const* d_in, const int* in_sizes, int n_in,
                              void* d_out, int out_size) {
    const float* source  = (const float*)d_in[0];
    const float* motions = (const float*)d_in[1];
    if (n_in >= 2 && in_sizes[0] != SRC_ELEMS) {
        source  = (const float*)d_in[1];
        motions = (const float*)d_in[0];
    }

    pack_src_kernel<<<4 * QROWS, PACK_THREADS>>>(source);

    // deform with programmatic dependent launch: prologue overlaps the packer
    cudaLaunchConfig_t cfg = {};
    cfg.gridDim  = dim3(NDEFB, 1, 1);
    cfg.blockDim = dim3(DTHREADS, 1, 1);
    cfg.dynamicSmemBytes = 0;
    cfg.stream = 0;
    cudaLaunchAttribute attrs[1];
    attrs[0].id = cudaLaunchAttributeProgrammaticStreamSerialization;
    attrs[0].val.programmaticStreamSerializationAllowed = 1;
    cfg.attrs = attrs;
    cfg.numAttrs = 1;
    cudaError_t e = cudaLaunchKernelEx(&cfg, deform_kernel,
                                       motions, (float*)d_out);
    if (e != cudaSuccess) {
        deform_kernel<<<NDEFB, DTHREADS>>>(motions, (float*)d_out);
    }
}